// round 3
// baseline (speedup 1.0000x reference)
#include <cuda_runtime.h>
#include <cuda_bf16.h>
#include <mma.h>
#include <cstdint>

using namespace nvcuda;

// Problem constants
#define B_DIM    32
#define S_DIM    2048
#define H_DIM    4096
#define R_DIM    64
#define TILE_M   128
#define KC       32                    // K elements per chunk
#define NCHUNK   (H_DIM / KC)          // 128
#define NTHREADS 256
#define NSTAGE   4

// SMEM layout: padded row stride to dodge bank conflicts
#define LDX        36                  // floats per row (32 + 4 pad)
#define LDW        36
#define X_STAGE_F  (TILE_M * LDX)      // 4608 floats = 18432 B
#define W_STAGE_F  (R_DIM * LDW)       // 2304 floats = 9216 B
#define STAGE_F    (X_STAGE_F + W_STAGE_F)        // 6912 floats
#define STAGE_B    (STAGE_F * 4)                  // 27648 B
#define SMEM_TOTAL (NSTAGE * STAGE_B)             // 110592 B

__device__ __forceinline__ uint32_t f32_to_tf32(float f) {
    uint32_t u;
    asm("cvt.rna.tf32.f32 %0, %1;" : "=r"(u) : "f"(f));
    return u;
}

__device__ __forceinline__ uint32_t smem_u32(const void* p) {
    uint32_t r;
    asm("{ .reg .u64 t; cvta.to.shared.u64 t, %1; cvt.u32.u64 %0, t; }"
        : "=r"(r) : "l"(p));
    return r;
}

__device__ __forceinline__ void cp_async16(uint32_t dst, const void* src) {
    asm volatile("cp.async.cg.shared.global [%0], [%1], 16;"
                 :: "r"(dst), "l"(src) : "memory");
}
#define CP_COMMIT() asm volatile("cp.async.commit_group;" ::: "memory")
#define CP_WAIT2()  asm volatile("cp.async.wait_group 2;" ::: "memory")

__global__ void __launch_bounds__(NTHREADS, 2)
multilora_wmma_kernel(const float* __restrict__ x,
                      const int* __restrict__ adapter_ids,
                      const float* __restrict__ weight,
                      float* __restrict__ out) {
    extern __shared__ __align__(16) float smem[];
    const uint32_t smem_base = smem_u32(smem);

    const int tid = threadIdx.x;
    const int wid = tid >> 5;

    const int mtile = blockIdx.x;       // 0..15
    const int b     = blockIdx.y;       // 0..31
    const int m0    = mtile * TILE_M;
    const int aid   = __ldg(adapter_ids + b);

    // ---- producer mapping: 1536 16B quads / chunk over 256 threads = 6 each
    // quads [0,1024): x tile (row = i/8, q = i%8); [1024,1536): w tile.
    const float* gbase[6];
    uint32_t soff[6];                   // byte offset within one stage buffer
    #pragma unroll
    for (int j = 0; j < 6; j++) {
        int i = tid + j * NTHREADS;
        if (i < 1024) {
            int row = i >> 3, q = i & 7;
            gbase[j] = x + ((size_t)(b * S_DIM + m0 + row)) * H_DIM + q * 4;
            soff[j]  = (uint32_t)((row * LDX + q * 4) * 4);
        } else {
            int t = i - 1024;
            int row = t >> 3, q = t & 7;
            gbase[j] = weight + ((size_t)(aid * R_DIM + row)) * H_DIM + q * 4;
            soff[j]  = (uint32_t)(X_STAGE_F * 4 + (row * LDW + q * 4) * 4);
        }
    }

    // ---- consumer mapping: 8 warps, 32x32 warp tiles (4 along M, 2 along N)
    const int wm = wid >> 1;
    const int wn = wid & 1;

    wmma::fragment<wmma::accumulator, 16, 16, 8, float> acc[2][2];
    #pragma unroll
    for (int fi = 0; fi < 2; fi++)
        #pragma unroll
        for (int fj = 0; fj < 2; fj++)
            wmma::fill_fragment(acc[fi][fj], 0.0f);

    // ---- prologue: fill stages 0..2
    #pragma unroll
    for (int p = 0; p < NSTAGE - 1; p++) {
        uint32_t sb = smem_base + p * STAGE_B;
        #pragma unroll
        for (int j = 0; j < 6; j++)
            cp_async16(sb + soff[j], gbase[j] + (size_t)p * KC);
        CP_COMMIT();
    }

    for (int kc = 0; kc < NCHUNK; kc++) {
        // stage kc is complete once only the 2 newest groups may be pending
        CP_WAIT2();
        __syncthreads();   // visibility of stage kc; proves compute(kc-1) done
                           // -> slot (kc+3)&3 == (kc-1)&3 is WAR-safe below

        if (kc + NSTAGE - 1 < NCHUNK) {
            uint32_t sb = smem_base + ((kc + NSTAGE - 1) & (NSTAGE - 1)) * STAGE_B;
            #pragma unroll
            for (int j = 0; j < 6; j++)
                cp_async16(sb + soff[j], gbase[j] + (size_t)(kc + NSTAGE - 1) * KC);
        }
        CP_COMMIT();       // unconditional: keeps group<->stage alignment

        float* xs = smem + (kc & (NSTAGE - 1)) * STAGE_F;
        float* ws = xs + X_STAGE_F;

        #pragma unroll
        for (int kk = 0; kk < KC; kk += 8) {
            wmma::fragment<wmma::matrix_a, 16, 16, 8, wmma::precision::tf32,
                           wmma::row_major> af[2];
            wmma::fragment<wmma::matrix_b, 16, 16, 8, wmma::precision::tf32,
                           wmma::col_major> bf[2];
            #pragma unroll
            for (int fi = 0; fi < 2; fi++) {
                wmma::load_matrix_sync(af[fi],
                    xs + (wm * 32 + fi * 16) * LDX + kk, LDX);
                #pragma unroll
                for (int e = 0; e < af[fi].num_elements; e++)
                    af[fi].x[e] = __uint_as_float(f32_to_tf32(af[fi].x[e]));
            }
            #pragma unroll
            for (int fj = 0; fj < 2; fj++) {
                wmma::load_matrix_sync(bf[fj],
                    ws + (wn * 32 + fj * 16) * LDW + kk, LDW);
                #pragma unroll
                for (int e = 0; e < bf[fj].num_elements; e++)
                    bf[fj].x[e] = __uint_as_float(f32_to_tf32(bf[fj].x[e]));
            }
            #pragma unroll
            for (int fi = 0; fi < 2; fi++)
                #pragma unroll
                for (int fj = 0; fj < 2; fj++)
                    wmma::mma_sync(acc[fi][fj], af[fi], bf[fj], acc[fi][fj]);
        }
    }

    // ---- epilogue: direct store, out is [B, S, R] row-major
    float* obase = out + ((size_t)(b * S_DIM + m0 + wm * 32)) * R_DIM + wn * 32;
    #pragma unroll
    for (int fi = 0; fi < 2; fi++)
        #pragma unroll
        for (int fj = 0; fj < 2; fj++)
            wmma::store_matrix_sync(obase + (size_t)fi * 16 * R_DIM + fj * 16,
                                    acc[fi][fj], R_DIM, wmma::mem_row_major);
}

extern "C" void kernel_launch(void* const* d_in, const int* in_sizes, int n_in,
                              void* d_out, int out_size) {
    const float* x   = (const float*)d_in[0];
    const int*   ids = (const int*)d_in[1];
    const float* w   = (const float*)d_in[2];
    float* out = (float*)d_out;

    const int b = in_sizes[1];   // number of requests (32)

    cudaFuncSetAttribute(multilora_wmma_kernel,
                         cudaFuncAttributeMaxDynamicSharedMemorySize, SMEM_TOTAL);

    dim3 grid(S_DIM / TILE_M, b);
    multilora_wmma_kernel<<<grid, NTHREADS, SMEM_TOTAL>>>(x, ids, w, out);
}

// round 4
// speedup vs baseline: 1.0088x; 1.0088x over previous
#include <cuda_runtime.h>
#include <cuda_bf16.h>
#include <mma.h>
#include <cstdint>

using namespace nvcuda;

// Problem constants
#define B_DIM    32
#define S_DIM    2048
#define H_DIM    4096
#define R_DIM    64
#define TILE_M   128
#define KC       32                    // K elements per chunk
#define NCHUNK   (H_DIM / KC)          // 128
#define NSTAGE   4
#define NTHREADS 384                   // 8 consumer warps + 4 producer warps

// SMEM: [0,64) mbarriers (full[4] then empty[4]), buffers at 64.
// Padded row stride (36 floats) -> conflict-free LDS and STS.128.
#define LDX        36
#define LDW        36
#define X_STAGE_F  (TILE_M * LDX)                  // 4608 floats
#define W_STAGE_F  (R_DIM * LDW)                   // 2304 floats
#define STAGE_F    (X_STAGE_F + W_STAGE_F)         // 6912 floats
#define STAGE_B    (STAGE_F * 4)                   // 27648 B
#define SMEM_BUF   64
#define SMEM_TOTAL (SMEM_BUF + NSTAGE * STAGE_B)   // 110656 B (2 CTAs = 221312 <= 228KB)

__device__ __forceinline__ uint32_t f32_to_tf32(float f) {
    uint32_t u;
    asm("cvt.rna.tf32.f32 %0, %1;" : "=r"(u) : "f"(f));
    return u;
}

__device__ __forceinline__ uint32_t smem_u32(const void* p) {
    uint32_t r;
    asm("{ .reg .u64 t; cvta.to.shared.u64 t, %1; cvt.u32.u64 %0, t; }"
        : "=r"(r) : "l"(p));
    return r;
}

__device__ __forceinline__ void sts128(uint32_t addr, uint32_t a, uint32_t b,
                                       uint32_t c, uint32_t d) {
    asm volatile("st.shared.v4.b32 [%0], {%1, %2, %3, %4};"
                 :: "r"(addr), "r"(a), "r"(b), "r"(c), "r"(d));
}

#define MBAR_INIT(addr, cnt) \
    asm volatile("mbarrier.init.shared.b64 [%0], %1;" \
                 :: "r"(addr), "r"(cnt) : "memory")

#define MBAR_ARRIVE(addr) \
    asm volatile("mbarrier.arrive.shared.b64 _, [%0];" \
                 :: "r"(addr) : "memory")

__device__ __forceinline__ void mbar_wait(uint32_t addr, uint32_t parity) {
    uint32_t done;
    asm volatile(
        "{\n\t.reg .pred p;\n\t"
        "mbarrier.try_wait.parity.acquire.cta.shared::cta.b64 p, [%1], %2;\n\t"
        "selp.b32 %0, 1, 0, p;\n\t}"
        : "=r"(done) : "r"(addr), "r"(parity) : "memory");
    if (!done) {
        asm volatile(
            "{\n\t.reg .pred P1;\n\t"
            "WAIT_LOOP_%=:\n\t"
            "mbarrier.try_wait.parity.acquire.cta.shared::cta.b64 P1, [%0], %1, 0x989680;\n\t"
            "@P1 bra.uni WAIT_DONE_%=;\n\t"
            "bra.uni WAIT_LOOP_%=;\n\t"
            "WAIT_DONE_%=:\n\t}"
            :: "r"(addr), "r"(parity) : "memory");
    }
}

__global__ void __launch_bounds__(NTHREADS, 2)
multilora_ws_kernel(const float* __restrict__ x,
                    const int* __restrict__ adapter_ids,
                    const float* __restrict__ weight,
                    float* __restrict__ out) {
    extern __shared__ __align__(16) float smem[];
    const uint32_t smem_base = smem_u32(smem);
    float* buf = smem + SMEM_BUF / 4;

    const int tid = threadIdx.x;
    const int wid = tid >> 5;

    const int mtile = blockIdx.x;       // 0..15
    const int b     = blockIdx.y;       // 0..31
    const int m0    = mtile * TILE_M;

    // mbarriers: full[s] at 8*s, empty[s] at 32 + 8*s
    const uint32_t FULL0  = smem_base;
    const uint32_t EMPTY0 = smem_base + 32;

    if (tid == 0) {
        #pragma unroll
        for (int s = 0; s < NSTAGE; s++) {
            MBAR_INIT(FULL0  + 8 * s, 128);   // 4 producer warps arrive
            MBAR_INIT(EMPTY0 + 8 * s, 256);   // 8 consumer warps arrive
        }
    }
    __syncthreads();

    if (wid < 8) {
        // ================= CONSUMER: 8 warps, 32x32 WMMA tiles ==============
        // Pre-arm empty barriers (completes phase 0 -> producers' first waits pass)
        #pragma unroll
        for (int s = 0; s < NSTAGE; s++)
            MBAR_ARRIVE(EMPTY0 + 8 * s);

        const int wm = wid >> 1;
        const int wn = wid & 1;

        wmma::fragment<wmma::accumulator, 16, 16, 8, float> acc[2][2];
        #pragma unroll
        for (int fi = 0; fi < 2; fi++)
            #pragma unroll
            for (int fj = 0; fj < 2; fj++)
                wmma::fill_fragment(acc[fi][fj], 0.0f);

        for (int kc = 0; kc < NCHUNK; kc++) {
            const int s = kc & (NSTAGE - 1);
            const uint32_t parity = (uint32_t)(kc >> 2) & 1u;
            mbar_wait(FULL0 + 8 * s, parity);

            const float* xs = buf + s * STAGE_F;
            const float* ws = xs + X_STAGE_F;

            #pragma unroll
            for (int kk = 0; kk < KC; kk += 8) {
                wmma::fragment<wmma::matrix_a, 16, 16, 8, wmma::precision::tf32,
                               wmma::row_major> af[2];
                wmma::fragment<wmma::matrix_b, 16, 16, 8, wmma::precision::tf32,
                               wmma::col_major> bf[2];
                #pragma unroll
                for (int fi = 0; fi < 2; fi++)
                    wmma::load_matrix_sync(af[fi],
                        xs + (wm * 32 + fi * 16) * LDX + kk, LDX);
                #pragma unroll
                for (int fj = 0; fj < 2; fj++)
                    wmma::load_matrix_sync(bf[fj],
                        ws + (wn * 32 + fj * 16) * LDW + kk, LDW);
                #pragma unroll
                for (int fi = 0; fi < 2; fi++)
                    #pragma unroll
                    for (int fj = 0; fj < 2; fj++)
                        wmma::mma_sync(acc[fi][fj], af[fi], bf[fj], acc[fi][fj]);
            }

            // all LDS for this stage done (fragments in registers)
            MBAR_ARRIVE(EMPTY0 + 8 * s);
        }

        // epilogue: direct store, out is [B, S, R] row-major
        float* obase = out + ((size_t)(b * S_DIM + m0 + wm * 32)) * R_DIM + wn * 32;
        #pragma unroll
        for (int fi = 0; fi < 2; fi++)
            #pragma unroll
            for (int fj = 0; fj < 2; fj++)
                wmma::store_matrix_sync(obase + (size_t)fi * 16 * R_DIM + fj * 16,
                                        acc[fi][fj], R_DIM, wmma::mem_row_major);
    } else {
        // ================= PRODUCER: 4 warps, LDG -> CVT.RNA -> STS =========
        const int ptid = tid - 256;                  // 0..127
        const int aid  = __ldg(adapter_ids + b);

        // x: 1024 quads/chunk -> 8 per thread; w: 512 quads -> 4 per thread
        const float* xg[8];
        uint32_t xoff[8];
        #pragma unroll
        for (int j = 0; j < 8; j++) {
            int i = ptid + j * 128;
            int row = i >> 3, q = i & 7;
            xg[j]   = x + ((size_t)(b * S_DIM + m0 + row)) * H_DIM + q * 4;
            xoff[j] = (uint32_t)(SMEM_BUF + (row * LDX + q * 4) * 4);
        }
        const float* wg[4];
        uint32_t woff[4];
        #pragma unroll
        for (int j = 0; j < 4; j++) {
            int i = ptid + j * 128;
            int row = i >> 3, q = i & 7;
            wg[j]   = weight + ((size_t)(aid * R_DIM + row)) * H_DIM + q * 4;
            woff[j] = (uint32_t)(SMEM_BUF + X_STAGE_F * 4 + (row * LDW + q * 4) * 4);
        }

        for (int kc = 0; kc < NCHUNK; kc++) {
            const int s = kc & (NSTAGE - 1);
            const uint32_t parity = (uint32_t)(kc >> 2) & 1u;
            const uint32_t sbase = smem_base + s * STAGE_B;
            const size_t gk = (size_t)kc * KC;

            mbar_wait(EMPTY0 + 8 * s, parity);

            // batched loads (MLP), then convert + store
            float4 vx[8];
            #pragma unroll
            for (int j = 0; j < 8; j++)
                vx[j] = *(const float4*)(xg[j] + gk);
            #pragma unroll
            for (int j = 0; j < 8; j++)
                sts128(sbase + xoff[j],
                       f32_to_tf32(vx[j].x), f32_to_tf32(vx[j].y),
                       f32_to_tf32(vx[j].z), f32_to_tf32(vx[j].w));

            float4 vw[4];
            #pragma unroll
            for (int j = 0; j < 4; j++)
                vw[j] = *(const float4*)(wg[j] + gk);
            #pragma unroll
            for (int j = 0; j < 4; j++)
                sts128(sbase + woff[j],
                       f32_to_tf32(vw[j].x), f32_to_tf32(vw[j].y),
                       f32_to_tf32(vw[j].z), f32_to_tf32(vw[j].w));

            MBAR_ARRIVE(FULL0 + 8 * s);
        }
    }
}

extern "C" void kernel_launch(void* const* d_in, const int* in_sizes, int n_in,
                              void* d_out, int out_size) {
    const float* x   = (const float*)d_in[0];
    const int*   ids = (const int*)d_in[1];
    const float* w   = (const float*)d_in[2];
    float* out = (float*)d_out;

    const int b = in_sizes[1];   // number of requests (32)

    cudaFuncSetAttribute(multilora_ws_kernel,
                         cudaFuncAttributeMaxDynamicSharedMemorySize, SMEM_TOTAL);

    dim3 grid(S_DIM / TILE_M, b);
    multilora_ws_kernel<<<grid, NTHREADS, SMEM_TOTAL>>>(x, ids, w, out);
}

// round 5
// speedup vs baseline: 2.5481x; 2.5260x over previous
#include <cuda_runtime.h>
#include <cuda_fp16.h>
#include <mma.h>
#include <cstdint>

using namespace nvcuda;

// Problem constants
#define B_DIM    32
#define S_DIM    2048
#define H_DIM    4096
#define R_DIM    64
#define TILE_M   128
#define KC       32                    // K elements per chunk
#define NCHUNK   (H_DIM / KC)          // 128
#define NTHREADS 256

// SMEM (half): row stride 40 halves = 80 B.
//  - WMMA ldm multiple of 8 halves (16B) ✓
//  - ldmatrix row offsets 80*r mod 128 are distinct for r=0..7 -> conflict-free
#define LDH        40                  // halves per row (32 + 8 pad)
#define X_STAGE_H  (TILE_M * LDH)      // 5120 halves = 10240 B
#define W_STAGE_H  (R_DIM * LDH)       // 2560 halves = 5120 B
#define STAGE_H    (X_STAGE_H + W_STAGE_H)        // 7680 halves
#define STAGE_B    (STAGE_H * 2)                  // 15360 B
#define SMEM_TOTAL (2 * STAGE_B)                  // 30720 B

__device__ __forceinline__ uint32_t smem_u32(const void* p) {
    uint32_t r;
    asm("{ .reg .u64 t; cvta.to.shared.u64 t, %1; cvt.u32.u64 %0, t; }"
        : "=r"(r) : "l"(p));
    return r;
}

__device__ __forceinline__ void sts64(uint32_t addr, uint32_t a, uint32_t b) {
    asm volatile("st.shared.v2.b32 [%0], {%1, %2};"
                 :: "r"(addr), "r"(a), "r"(b));
}

__global__ void __launch_bounds__(NTHREADS, 2)
multilora_fp16_kernel(const float* __restrict__ x,
                      const int* __restrict__ adapter_ids,
                      const float* __restrict__ weight,
                      float* __restrict__ out) {
    extern __shared__ __align__(16) __half smem[];
    const uint32_t smem_base = smem_u32(smem);

    const int tid = threadIdx.x;
    const int wid = tid >> 5;

    const int mtile = blockIdx.x;       // 0..15
    const int b     = blockIdx.y;       // 0..31
    const int m0    = mtile * TILE_M;
    const int aid   = __ldg(adapter_ids + b);

    // ---- producer mapping: 1536 float4 quads / chunk over 256 threads = 6 each
    // quads [0,1024): x tile (row = i/8, q = i%8); [1024,1536): w tile.
    const float* gptr[6];
    uint32_t sm_off[6];    // byte offset within a stage buffer
    #pragma unroll
    for (int j = 0; j < 6; j++) {
        int i = tid + j * NTHREADS;
        if (i < 1024) {
            int row = i >> 3, q = i & 7;
            gptr[j]  = x + ((size_t)(b * S_DIM + m0 + row)) * H_DIM + q * 4;
            sm_off[j] = (uint32_t)((row * LDH + q * 4) * 2);
        } else {
            int t = i - 1024;
            int row = t >> 3, q = t & 7;
            gptr[j]  = weight + ((size_t)(aid * R_DIM + row)) * H_DIM + q * 4;
            sm_off[j] = (uint32_t)((X_STAGE_H + row * LDH + q * 4) * 2);
        }
    }

    // ---- consumer mapping: 8 warps, 32x32 warp tiles (4 along M, 2 along N)
    const int wm = wid >> 1;
    const int wn = wid & 1;

    wmma::fragment<wmma::accumulator, 16, 16, 16, float> acc[2][2];
    #pragma unroll
    for (int fi = 0; fi < 2; fi++)
        #pragma unroll
        for (int fj = 0; fj < 2; fj++)
            wmma::fill_fragment(acc[fi][fj], 0.0f);

    // ---- register double buffer for global loads
    float4 cur[6], nxt[6];
    #pragma unroll
    for (int j = 0; j < 6; j++)
        cur[j] = *(const float4*)(gptr[j]);

    for (int kc = 0; kc < NCHUNK; kc++) {
        const int s = kc & 1;
        __half* xs = smem + s * STAGE_H;
        __half* ws = xs + X_STAGE_H;
        const uint32_t sbase = smem_base + s * STAGE_B;

        // prefetch next chunk into registers (hides DRAM latency under compute)
        if (kc + 1 < NCHUNK) {
            #pragma unroll
            for (int j = 0; j < 6; j++)
                nxt[j] = *(const float4*)(gptr[j] + (size_t)(kc + 1) * KC);
        }

        // RN convert f32 -> half2 pairs + STS.64
        #pragma unroll
        for (int j = 0; j < 6; j++) {
            __half2 h0 = __floats2half2_rn(cur[j].x, cur[j].y);
            __half2 h1 = __floats2half2_rn(cur[j].z, cur[j].w);
            sts64(sbase + sm_off[j],
                  *(const uint32_t*)&h0, *(const uint32_t*)&h1);
        }

        // Single barrier per chunk:
        //  - RAW: all STS(stage s) visible before compute(stage s)
        //  - WAR: compute(stage s^1) of iter kc-1 precedes this barrier in
        //    program order, so the next iter's STS(stage s^1) is safe.
        __syncthreads();

        // compute: 2 k-steps of m16n16k16
        #pragma unroll
        for (int kk = 0; kk < KC; kk += 16) {
            wmma::fragment<wmma::matrix_a, 16, 16, 16, __half,
                           wmma::row_major> af[2];
            wmma::fragment<wmma::matrix_b, 16, 16, 16, __half,
                           wmma::col_major> bf[2];
            #pragma unroll
            for (int fi = 0; fi < 2; fi++)
                wmma::load_matrix_sync(af[fi],
                    xs + (wm * 32 + fi * 16) * LDH + kk, LDH);
            #pragma unroll
            for (int fj = 0; fj < 2; fj++)
                wmma::load_matrix_sync(bf[fj],
                    ws + (wn * 32 + fj * 16) * LDH + kk, LDH);
            #pragma unroll
            for (int fi = 0; fi < 2; fi++)
                #pragma unroll
                for (int fj = 0; fj < 2; fj++)
                    wmma::mma_sync(acc[fi][fj], af[fi], bf[fj], acc[fi][fj]);
        }

        #pragma unroll
        for (int j = 0; j < 6; j++) cur[j] = nxt[j];
    }

    // ---- epilogue: direct store to gmem, out is [B, S, R] row-major
    float* obase = out + ((size_t)(b * S_DIM + m0 + wm * 32)) * R_DIM + wn * 32;
    #pragma unroll
    for (int fi = 0; fi < 2; fi++)
        #pragma unroll
        for (int fj = 0; fj < 2; fj++)
            wmma::store_matrix_sync(obase + (size_t)fi * 16 * R_DIM + fj * 16,
                                    acc[fi][fj], R_DIM, wmma::mem_row_major);
}

extern "C" void kernel_launch(void* const* d_in, const int* in_sizes, int n_in,
                              void* d_out, int out_size) {
    const float* x   = (const float*)d_in[0];
    const int*   ids = (const int*)d_in[1];
    const float* w   = (const float*)d_in[2];
    float* out = (float*)d_out;

    const int b = in_sizes[1];   // number of requests (32)

    cudaFuncSetAttribute(multilora_fp16_kernel,
                         cudaFuncAttributeMaxDynamicSharedMemorySize, SMEM_TOTAL);

    dim3 grid(S_DIM / TILE_M, b);
    multilora_fp16_kernel<<<grid, NTHREADS, SMEM_TOTAL>>>(x, ids, w, out);
}